// round 3
// baseline (speedup 1.0000x reference)
#include <cuda_runtime.h>

#define NB 4096
#define N1 16
#define N2 32
#define DD 30
#define NH 6
#define HDIM 5
#define LH 64
#define NEG 0.02f
#define ATT_SCALE 0.44721359549995793f  // 1/sqrt(5)

#define RS 48   // K/V shared row stride in floats (6 heads x 8)

// hop-2 output: [B*N1, 30]
__device__ float g_h1[NB * N1 * DD];

// ---------------------------------------------------------------------------
// dot of 30-elem register vector (padded to 32 with zeros) against a shared
// weight row of 32 floats (pad zeroed), via float4 broadcast loads.
// ---------------------------------------------------------------------------
__device__ __forceinline__ float dot32(const float* __restrict__ wrow,
                                       const float (&v)[32]) {
    const float4* w4 = (const float4*)wrow;
    float a0 = 0.f, a1 = 0.f;
#pragma unroll
    for (int kk = 0; kk < 8; kk += 2) {
        float4 wa = w4[kk];
        float4 wb = w4[kk + 1];
        a0 += v[4 * kk + 0] * wa.x; a0 += v[4 * kk + 1] * wa.y;
        a0 += v[4 * kk + 2] * wa.z; a0 += v[4 * kk + 3] * wa.w;
        a1 += v[4 * kk + 4] * wb.x; a1 += v[4 * kk + 5] * wb.y;
        a1 += v[4 * kk + 6] * wb.z; a1 += v[4 * kk + 7] * wb.w;
    }
    return a0 + a1;
}

// ===========================================================================
// Kernel 1: second hop. 4 sequences per CTA (one per warp), S=32 rows = lanes.
// smem: weights 150x32 (rows: lw 0-29, iw 30-119, ow 120-149) + biases + K/V.
// K row: 32 x RS floats; V row likewise.
// ===========================================================================
#define KV1_PER_SEQ (2 * 32 * RS)                 // 3072
#define SMEM1_FLOATS (4960 + 4 * KV1_PER_SEQ)     // 17248

__global__ void __launch_bounds__(128) hop2_kernel(
    const float* __restrict__ x2,
    const float* __restrict__ lw, const float* __restrict__ lb,
    const float* __restrict__ iw, const float* __restrict__ ib,
    const float* __restrict__ ow, const float* __restrict__ ob) {
    extern __shared__ float sm[];
    float* lw_s = sm;                 // rows 0..29   (x32)
    float* iw_s = sm + 30 * 32;       // rows 30..119 (x32)
    float* ow_s = sm + 120 * 32;      // rows 120..149(x32)
    float* lb_s = sm + 4800;          // 32
    float* ib_s = sm + 4832;          // 96
    float* ob_s = sm + 4928;          // 32
    float* kv   = sm + 4960;          // 4 * (K 1536 + V 1536)

    const int tid = threadIdx.x;

    for (int i = tid; i < 4800; i += 128) {
        int row = i >> 5, col = i & 31;
        float v = 0.f;
        if (col < 30) {
            if (row < 30)       v = lw[row * 30 + col];
            else if (row < 120) v = iw[(row - 30) * 30 + col];
            else                v = ow[(row - 120) * 30 + col];
        }
        sm[i] = v;
    }
    if (tid < 30) lb_s[tid] = lb[tid];
    if (tid < 90) ib_s[tid] = ib[tid];
    if (tid < 30) ob_s[tid] = ob[tid];
    __syncthreads();

    const int seq = tid >> 5;
    const int r   = tid & 31;
    const long seqG = (long)blockIdx.x * 4 + seq;

    float* Ks = kv + seq * KV1_PER_SEQ;
    float* Vs = Ks + 32 * RS;

    // ---- stage 1: y = leaky(x @ lw^T + lb) --------------------------------
    const float* xp = x2 + (seqG * 32 + r) * 30;
    float xr[32];
#pragma unroll
    for (int k2 = 0; k2 < 15; k2++) {
        float2 t = *(const float2*)(xp + 2 * k2);
        xr[2 * k2] = t.x; xr[2 * k2 + 1] = t.y;
    }
    xr[30] = 0.f; xr[31] = 0.f;

    float y[32];
#pragma unroll
    for (int j = 0; j < 30; j++) {
        float acc = lb_s[j] + dot32(lw_s + j * 32, xr);
        y[j] = fmaxf(acc, NEG * acc);
    }
    y[30] = 0.f; y[31] = 0.f;

    // ---- stage 2: qkv ------------------------------------------------------
    float q[30];
#pragma unroll
    for (int j = 0; j < 30; j++)
        q[j] = ib_s[j] + dot32(iw_s + j * 32, y);

#pragma unroll 1
    for (int hv = 0; hv < 2; hv++) {
        float* dst = hv ? Vs : Ks;
#pragma unroll 1
        for (int hh = 0; hh < 6; hh++) {
#pragma unroll
            for (int d = 0; d < 5; d++) {
                int j = 30 + hv * 30 + hh * 5 + d;
                float acc = ib_s[j] + dot32(iw_s + j * 32, y);
                dst[r * RS + hh * 8 + d] = acc;
            }
        }
    }
    __syncwarp();

    // ---- stage 3: attention ------------------------------------------------
    float o[32];
#pragma unroll
    for (int j = 0; j < 32; j++) o[j] = 0.f;

#pragma unroll
    for (int h = 0; h < 6; h++) {
        float q0 = q[h * 5], q1 = q[h * 5 + 1], q2 = q[h * 5 + 2];
        float q3 = q[h * 5 + 3], q4 = q[h * 5 + 4];
        float sc[32];
        float mx = -3.4e38f;
#pragma unroll
        for (int t = 0; t < 32; t++) {
            float4 k4 = *(const float4*)(Ks + t * RS + h * 8);
            float k5 = Ks[t * RS + h * 8 + 4];
            float s = q0 * k4.x + q1 * k4.y + q2 * k4.z + q3 * k4.w + q4 * k5;
            s *= ATT_SCALE;
            sc[t] = s;
            mx = fmaxf(mx, s);
        }
        float sum = 0.f;
#pragma unroll
        for (int t = 0; t < 32; t++) {
            float e = __expf(sc[t] - mx);
            sc[t] = e;
            sum += e;
        }
        float inv = 1.f / sum;
        float a0 = 0.f, a1 = 0.f, a2 = 0.f, a3 = 0.f, a4 = 0.f;
#pragma unroll
        for (int t = 0; t < 32; t++) {
            float p = sc[t];
            float4 v4 = *(const float4*)(Vs + t * RS + h * 8);
            float v5 = Vs[t * RS + h * 8 + 4];
            a0 += p * v4.x; a1 += p * v4.y; a2 += p * v4.z;
            a3 += p * v4.w; a4 += p * v5;
        }
        o[h * 5 + 0] = a0 * inv; o[h * 5 + 1] = a1 * inv;
        o[h * 5 + 2] = a2 * inv; o[h * 5 + 3] = a3 * inv;
        o[h * 5 + 4] = a4 * inv;
    }

    // ---- stage 4: out-proj + mean over rows --------------------------------
    __syncwarp();              // all lanes done reading Ks before reuse
    float* red = Ks;           // reuse [32][RS]
#pragma unroll 1
    for (int j = 0; j < 30; j++) {
        float acc = ob_s[j] + dot32(ow_s + j * 32, o);
        red[r * RS + j] = acc;
    }
    __syncwarp();
    if (r < 30) {
        float s = 0.f;
#pragma unroll
        for (int t = 0; t < 32; t++) s += red[t * RS + r];
        g_h1[seqG * 30 + r] = s * (1.f / 32.f);
    }
}

// ===========================================================================
// Kernel 2: first hop (S=17) + classifier MLP + softmax. 4 nodes per CTA.
// ===========================================================================
#define KV2_PER_SEQ (2 * 17 * RS)                 // 1632
#define OFF_KV2   4960
#define OFF_CW1P  (OFF_KV2 + 4 * KV2_PER_SEQ)     // 11488
#define OFF_CB1   (OFF_CW1P + 64 * 31)            // 13472
#define OFF_CW2P  (OFF_CB1 + 64)                  // 13536
#define OFF_CB2   (OFF_CW2P + 64 * 65)            // 17696
#define OFF_CW3   (OFF_CB2 + 64)                  // 17760
#define OFF_CB3   (OFF_CW3 + 128)                 // 17888
#define OFF_EMB   (OFF_CB3 + 4)                   // 17892
#define OFF_HA    (OFF_EMB + 128)                 // 18020
#define OFF_HB    (OFF_HA + 256)                  // 18276
#define SMEM2_FLOATS (OFF_HB + 256)               // 18532

__global__ void __launch_bounds__(128) hop1_kernel(
    const float* __restrict__ self_feat,
    const float* __restrict__ lw, const float* __restrict__ lb,
    const float* __restrict__ iw, const float* __restrict__ ib,
    const float* __restrict__ ow, const float* __restrict__ ob,
    const float* __restrict__ cw1, const float* __restrict__ cb1,
    const float* __restrict__ cw2, const float* __restrict__ cb2,
    const float* __restrict__ cw3, const float* __restrict__ cb3,
    float* __restrict__ out) {
    extern __shared__ float sm[];
    float* lw_s  = sm;                // 30 x 32
    float* iw_s  = sm + 30 * 32;      // 90 x 32
    float* ow_s  = sm + 120 * 32;     // 30 x 32
    float* lb_s  = sm + 4800;
    float* ib_s  = sm + 4832;
    float* ob_s  = sm + 4928;
    float* kv    = sm + OFF_KV2;
    float* cw1p  = sm + OFF_CW1P;     // 64 x 31
    float* cb1s  = sm + OFF_CB1;      // 64
    float* cw2p  = sm + OFF_CW2P;     // 64 x 65
    float* cb2s  = sm + OFF_CB2;      // 64
    float* cw3s  = sm + OFF_CW3;      // 128
    float* cb3s  = sm + OFF_CB3;      // 4
    float* embS  = sm + OFF_EMB;      // 4 x 32
    float* hA    = sm + OFF_HA;       // 4 x 64
    float* hB    = sm + OFF_HB;       // 4 x 64

    const int tid = threadIdx.x;

    for (int i = tid; i < 4800; i += 128) {
        int row = i >> 5, col = i & 31;
        float v = 0.f;
        if (col < 30) {
            if (row < 30)       v = lw[row * 30 + col];
            else if (row < 120) v = iw[(row - 30) * 30 + col];
            else                v = ow[(row - 120) * 30 + col];
        }
        sm[i] = v;
    }
    if (tid < 30) lb_s[tid] = lb[tid];
    if (tid < 90) ib_s[tid] = ib[tid];
    if (tid < 30) ob_s[tid] = ob[tid];
    for (int i = tid; i < 64 * 31; i += 128) {
        int row = i / 31, c = i % 31;
        cw1p[i] = (c < 30) ? cw1[row * 30 + c] : 0.f;
    }
    for (int i = tid; i < 64 * 65; i += 128) {
        int row = i / 65, c = i % 65;
        cw2p[i] = (c < 64) ? cw2[row * 64 + c] : 0.f;
    }
    if (tid < 64) { cb1s[tid] = cb1[tid]; cb2s[tid] = cb2[tid]; }
    if (tid < 128) cw3s[tid] = cw3[tid];
    if (tid < 2) cb3s[tid] = cb3[tid];
    __syncthreads();

    const int seq = tid >> 5;
    const int r   = tid & 31;
    const int b   = blockIdx.x * 4 + seq;

    float* Ks = kv + seq * KV2_PER_SEQ;
    float* Vs = Ks + 17 * RS;

    if (r < 17) {
        // ---- gather row: h1 rows 0..15, self_feat as row 16 ----------------
        const float* xp = (r < 16) ? (g_h1 + ((long)b * 16 + r) * 30)
                                   : (self_feat + (long)b * 30);
        float xr[32];
#pragma unroll
        for (int k2 = 0; k2 < 15; k2++) {
            float2 t = *(const float2*)(xp + 2 * k2);
            xr[2 * k2] = t.x; xr[2 * k2 + 1] = t.y;
        }
        xr[30] = 0.f; xr[31] = 0.f;

        float y[32];
#pragma unroll
        for (int j = 0; j < 30; j++) {
            float acc = lb_s[j] + dot32(lw_s + j * 32, xr);
            y[j] = fmaxf(acc, NEG * acc);
        }
        y[30] = 0.f; y[31] = 0.f;

        float q[30];
#pragma unroll
        for (int j = 0; j < 30; j++)
            q[j] = ib_s[j] + dot32(iw_s + j * 32, y);

#pragma unroll 1
        for (int hv = 0; hv < 2; hv++) {
            float* dst = hv ? Vs : Ks;
#pragma unroll 1
            for (int hh = 0; hh < 6; hh++) {
#pragma unroll
                for (int d = 0; d < 5; d++) {
                    int j = 30 + hv * 30 + hh * 5 + d;
                    float acc = ib_s[j] + dot32(iw_s + j * 32, y);
                    dst[r * RS + hh * 8 + d] = acc;
                }
            }
        }
        __syncwarp(0x0001FFFFu);

        float o[32];
#pragma unroll
        for (int j = 0; j < 32; j++) o[j] = 0.f;

#pragma unroll
        for (int h = 0; h < 6; h++) {
            float q0 = q[h * 5], q1 = q[h * 5 + 1], q2 = q[h * 5 + 2];
            float q3 = q[h * 5 + 3], q4 = q[h * 5 + 4];
            float sc[17];
            float mx = -3.4e38f;
#pragma unroll
            for (int t = 0; t < 17; t++) {
                float4 k4 = *(const float4*)(Ks + t * RS + h * 8);
                float k5 = Ks[t * RS + h * 8 + 4];
                float s = q0 * k4.x + q1 * k4.y + q2 * k4.z + q3 * k4.w + q4 * k5;
                s *= ATT_SCALE;
                sc[t] = s;
                mx = fmaxf(mx, s);
            }
            float sum = 0.f;
#pragma unroll
            for (int t = 0; t < 17; t++) {
                float e = __expf(sc[t] - mx);
                sc[t] = e;
                sum += e;
            }
            float inv = 1.f / sum;
            float a0 = 0.f, a1 = 0.f, a2 = 0.f, a3 = 0.f, a4 = 0.f;
#pragma unroll
            for (int t = 0; t < 17; t++) {
                float p = sc[t];
                float4 v4 = *(const float4*)(Vs + t * RS + h * 8);
                float v5 = Vs[t * RS + h * 8 + 4];
                a0 += p * v4.x; a1 += p * v4.y; a2 += p * v4.z;
                a3 += p * v4.w; a4 += p * v5;
            }
            o[h * 5 + 0] = a0 * inv; o[h * 5 + 1] = a1 * inv;
            o[h * 5 + 2] = a2 * inv; o[h * 5 + 3] = a3 * inv;
            o[h * 5 + 4] = a4 * inv;
        }

        __syncwarp(0x0001FFFFu);   // readers of Ks done before reuse
        float* red = Ks;           // reuse [17][RS]
#pragma unroll 1
        for (int j = 0; j < 30; j++) {
            float acc = ob_s[j] + dot32(ow_s + j * 32, o);
            red[r * RS + j] = acc;
        }
    }
    __syncwarp();
    if (r < 30) {
        float s = 0.f;
        float* red = Ks;
#pragma unroll
        for (int t = 0; t < 17; t++) s += red[t * RS + r];
        embS[seq * 32 + r] = s * (1.f / 17.f);
    }
    __syncwarp();

    // ---- classifier MLP (whole warp) --------------------------------------
    const float* emb = embS + seq * 32;
#pragma unroll
    for (int half = 0; half < 2; half++) {
        int j = r + 32 * half;
        float acc = cb1s[j];
#pragma unroll
        for (int k = 0; k < 30; k++) acc += emb[k] * cw1p[j * 31 + k];
        hA[seq * 64 + j] = fmaxf(acc, NEG * acc);
    }
    __syncwarp();
#pragma unroll
    for (int half = 0; half < 2; half++) {
        int j = r + 32 * half;
        float acc = cb2s[j];
#pragma unroll
        for (int k = 0; k < 64; k++) acc += hA[seq * 64 + k] * cw2p[j * 65 + k];
        hB[seq * 64 + j] = fmaxf(acc, NEG * acc);
    }
    __syncwarp();
    if (r < 2) {
        float acc = cb3s[r];
#pragma unroll
        for (int k = 0; k < 64; k++) acc += hB[seq * 64 + k] * cw3s[r * 64 + k];
        embS[seq * 32 + 30 + r] = acc;   // stash logits in spare emb slots
    }
    __syncwarp();
    if (r == 0) {
        float l0 = embS[seq * 32 + 30], l1 = embS[seq * 32 + 31];
        float m = fmaxf(l0, l1);
        float e0 = __expf(l0 - m), e1 = __expf(l1 - m);
        float inv = 1.f / (e0 + e1);
        out[(long)b * 2 + 0] = e0 * inv;
        out[(long)b * 2 + 1] = e1 * inv;
    }
}

// ===========================================================================
extern "C" void kernel_launch(void* const* d_in, const int* in_sizes, int n_in,
                              void* d_out, int out_size) {
    const float* x2   = (const float*)d_in[0];
    const float* self = (const float*)d_in[1];
    const float* lw2  = (const float*)d_in[2];
    const float* lb2  = (const float*)d_in[3];
    const float* iw2  = (const float*)d_in[4];
    const float* ib2  = (const float*)d_in[5];
    const float* ow2  = (const float*)d_in[6];
    const float* ob2  = (const float*)d_in[7];
    const float* lw1  = (const float*)d_in[8];
    const float* lb1  = (const float*)d_in[9];
    const float* iw1  = (const float*)d_in[10];
    const float* ib1  = (const float*)d_in[11];
    const float* ow1  = (const float*)d_in[12];
    const float* ob1  = (const float*)d_in[13];
    const float* cw1  = (const float*)d_in[14];
    const float* cb1  = (const float*)d_in[15];
    const float* cw2  = (const float*)d_in[16];
    const float* cb2  = (const float*)d_in[17];
    const float* cw3  = (const float*)d_in[18];
    const float* cb3  = (const float*)d_in[19];
    float* out = (float*)d_out;

    const int smem1 = SMEM1_FLOATS * 4;
    const int smem2 = SMEM2_FLOATS * 4;
    cudaFuncSetAttribute(hop2_kernel,
                         cudaFuncAttributeMaxDynamicSharedMemorySize, smem1);
    cudaFuncSetAttribute(hop1_kernel,
                         cudaFuncAttributeMaxDynamicSharedMemorySize, smem2);

    hop2_kernel<<<(NB * N1) / 4, 128, smem1>>>(x2, lw2, lb2, iw2, ib2, ow2, ob2);
    hop1_kernel<<<NB / 4, 128, smem2>>>(self, lw1, lb1, iw1, ib1, ow1, ob1,
                                        cw1, cb1, cw2, cb2, cw3, cb3, out);
}

// round 4
// speedup vs baseline: 1.1588x; 1.1588x over previous
#include <cuda_runtime.h>

#define NB 4096
#define NEG 0.02f
// (1/sqrt(5)) * log2(e)
#define CEXP 0.6451928329f

typedef unsigned long long u64;

// hop-2 output: [B*N1, 30]
__device__ float g_h1[NB * 16 * 30];

// ---------------------------------------------------------------------------
__device__ __forceinline__ u64 pk2(float lo, float hi) {
    u64 v; asm("mov.b64 %0,{%1,%2};" : "=l"(v) : "f"(lo), "f"(hi)); return v;
}
__device__ __forceinline__ float2 upk2(u64 v) {
    float2 r; asm("mov.b64 {%0,%1},%2;" : "=f"(r.x), "=f"(r.y) : "l"(v)); return r;
}
__device__ __forceinline__ u64 f2fma(u64 a, u64 b, u64 c) {
    u64 d; asm("fma.rn.f32x2 %0,%1,%2,%3;" : "=l"(d) : "l"(a), "l"(b), "l"(c));
    return d;
}
__device__ __forceinline__ float ex2f(float x) {
    float r; asm("ex2.approx.f32 %0,%1;" : "=f"(r) : "f"(x)); return r;
}
__device__ __forceinline__ float rcpf(float x) {
    float r; asm("rcp.approx.f32 %0,%1;" : "=f"(r) : "f"(x)); return r;
}

// packed dot: 32-float weight row (pad zeroed) vs 16 packed f32x2 regs
__device__ __forceinline__ float dotp(const float* __restrict__ wrow,
                                      const u64 (&v)[16]) {
    const ulonglong2* w2 = (const ulonglong2*)wrow;
    u64 a0 = 0ull, a1 = 0ull;
#pragma unroll
    for (int kk = 0; kk < 4; kk++) {
        ulonglong2 wa = w2[2 * kk];
        ulonglong2 wb = w2[2 * kk + 1];
        a0 = f2fma(wa.x, v[4 * kk + 0], a0);
        a1 = f2fma(wa.y, v[4 * kk + 1], a1);
        a0 = f2fma(wb.x, v[4 * kk + 2], a0);
        a1 = f2fma(wb.y, v[4 * kk + 3], a1);
    }
    float2 x = upk2(a0), y = upk2(a1);
    return (x.x + x.y) + (y.x + y.y);
}

// ---------------------------------------------------------------------------
// One GraphLayer for one sequence handled by one warp. Lane r = row r (r < S).
// sm: weight block (lw 0..959, iw 960..3839, ow 3840..4799, lb 4800, ib 4832,
//     ob 4928). buf: 1056-float per-seq scratch.
// Returns: lanes r<30 hold mean over rows; others undefined.
// ---------------------------------------------------------------------------
#define BUFF 1056

template <int S, bool FULL>
__device__ __forceinline__ float run_layer(int r,
                                           const float* __restrict__ xrow,
                                           const float* __restrict__ sm,
                                           float* __restrict__ buf,
                                           float invS) {
    const float* lw_s = sm;
    const float* iw_s = sm + 960;
    const float* ow_s = sm + 3840;
    const float* lb_s = sm + 4800;
    const float* ib_s = sm + 4832;
    const float* ob_s = sm + 4928;
    const bool act = FULL || (r < S);

    u64*   K01 = (u64*)buf;           // [2][32] packed (k0,k1),(k2,k3)
    float* K4  = buf + 128;           // [32]
    u64*   V01 = (u64*)(buf + 160);   // [2][32]
    float* V4  = buf + 288;           // [32]

    // ---- stage 1: y = leaky(x @ lw^T + lb), kept packed -------------------
    u64 yp[16];
    if (act) {
        u64 xp[16];
#pragma unroll
        for (int k = 0; k < 15; k++) {
            float2 t = *(const float2*)(xrow + 2 * k);
            xp[k] = pk2(t.x, t.y);
        }
        xp[15] = 0ull;
#pragma unroll
        for (int jj = 0; jj < 15; jj++) {
            float y0 = lb_s[2 * jj]     + dotp(lw_s + (2 * jj) * 32, xp);
            float y1 = lb_s[2 * jj + 1] + dotp(lw_s + (2 * jj + 1) * 32, xp);
            y0 = fmaxf(y0, NEG * y0);
            y1 = fmaxf(y1, NEG * y1);
            yp[jj] = pk2(y0, y1);
        }
        yp[15] = 0ull;
    }

    // ---- per-head qkv + attention (no-max softmax, single pass) -----------
    float o[30];
#pragma unroll
    for (int h = 0; h < 6; h++) {
        u64 q01 = 0ull, q23 = 0ull;
        float q4s = 0.f;
        if (act) {
            float q0 = (ib_s[h * 5 + 0] + dotp(iw_s + (h * 5 + 0) * 32, yp)) * CEXP;
            float q1 = (ib_s[h * 5 + 1] + dotp(iw_s + (h * 5 + 1) * 32, yp)) * CEXP;
            float q2 = (ib_s[h * 5 + 2] + dotp(iw_s + (h * 5 + 2) * 32, yp)) * CEXP;
            float q3 = (ib_s[h * 5 + 3] + dotp(iw_s + (h * 5 + 3) * 32, yp)) * CEXP;
            float q4 = (ib_s[h * 5 + 4] + dotp(iw_s + (h * 5 + 4) * 32, yp)) * CEXP;
            q01 = pk2(q0, q1); q23 = pk2(q2, q3); q4s = q4;

            float k0 = ib_s[30 + h * 5 + 0] + dotp(iw_s + (30 + h * 5 + 0) * 32, yp);
            float k1 = ib_s[30 + h * 5 + 1] + dotp(iw_s + (30 + h * 5 + 1) * 32, yp);
            float k2 = ib_s[30 + h * 5 + 2] + dotp(iw_s + (30 + h * 5 + 2) * 32, yp);
            float k3 = ib_s[30 + h * 5 + 3] + dotp(iw_s + (30 + h * 5 + 3) * 32, yp);
            float k4 = ib_s[30 + h * 5 + 4] + dotp(iw_s + (30 + h * 5 + 4) * 32, yp);
            float v0 = ib_s[60 + h * 5 + 0] + dotp(iw_s + (60 + h * 5 + 0) * 32, yp);
            float v1 = ib_s[60 + h * 5 + 1] + dotp(iw_s + (60 + h * 5 + 1) * 32, yp);
            float v2 = ib_s[60 + h * 5 + 2] + dotp(iw_s + (60 + h * 5 + 2) * 32, yp);
            float v3 = ib_s[60 + h * 5 + 3] + dotp(iw_s + (60 + h * 5 + 3) * 32, yp);
            float v4 = ib_s[60 + h * 5 + 4] + dotp(iw_s + (60 + h * 5 + 4) * 32, yp);

            K01[r]      = pk2(k0, k1);
            K01[32 + r] = pk2(k2, k3);
            K4[r]       = k4;
            V01[r]      = pk2(v0, v1);
            V01[32 + r] = pk2(v2, v3);
            V4[r]       = v4;
        }
        __syncwarp();
        if (act) {
            float sum = 0.f, a4 = 0.f;
            u64 a01 = 0ull, a23 = 0ull;
#pragma unroll 4
            for (int t = 0; t < S; t++) {
                u64 ka = K01[t], kb = K01[32 + t];
                float k4v = K4[t];
                u64 s2 = f2fma(ka, q01, f2fma(kb, q23, 0ull));
                float2 sp = upk2(s2);
                float s = fmaf(q4s, k4v, sp.x + sp.y);
                float e = ex2f(s);
                sum += e;
                u64 ee = pk2(e, e);
                a01 = f2fma(ee, V01[t], a01);
                a23 = f2fma(ee, V01[32 + t], a23);
                a4  = fmaf(e, V4[t], a4);
            }
            float inv = rcpf(sum);
            float2 p01 = upk2(a01), p23 = upk2(a23);
            o[h * 5 + 0] = p01.x * inv;
            o[h * 5 + 1] = p01.y * inv;
            o[h * 5 + 2] = p23.x * inv;
            o[h * 5 + 3] = p23.y * inv;
            o[h * 5 + 4] = a4 * inv;
        }
        __syncwarp();
    }

    // ---- out-proj + mean over rows ----------------------------------------
    float* red = buf;   // [S][33], overlaps K/V (synced above)
    if (act) {
        u64 op[16];
#pragma unroll
        for (int jj = 0; jj < 15; jj++) op[jj] = pk2(o[2 * jj], o[2 * jj + 1]);
        op[15] = 0ull;
#pragma unroll
        for (int j = 0; j < 30; j++)
            red[r * 33 + j] = ob_s[j] + dotp(ow_s + j * 32, op);
    }
    __syncwarp();
    float mean = 0.f;
    if (r < 30) {
#pragma unroll
        for (int t = 0; t < S; t++) mean += red[t * 33 + r];
        mean *= invS;
    }
    return mean;
}

// ---------------------------------------------------------------------------
__device__ __forceinline__ void stage_weights(float* sm, int tid, int nthr,
                                              const float* lw, const float* lb,
                                              const float* iw, const float* ib,
                                              const float* ow, const float* ob) {
    for (int i = tid; i < 4800; i += nthr) {
        int row = i >> 5, col = i & 31;
        float v = 0.f;
        if (col < 30) {
            if (row < 30)       v = lw[row * 30 + col];
            else if (row < 120) v = iw[(row - 30) * 30 + col];
            else                v = ow[(row - 120) * 30 + col];
        }
        sm[i] = v;
    }
    if (tid < 30) sm[4800 + tid] = lb[tid];
    if (tid < 90) sm[4832 + tid] = ib[tid];
    if (tid < 30) sm[4928 + tid] = ob[tid];
}

// ===========================================================================
// hop2: 8 sequences/CTA (one per warp), 65536 sequences total.
// ===========================================================================
#define WPC 8
#define SMEM1_FLOATS (4960 + WPC * BUFF)    // 13408 -> 53,632 B

__global__ void __launch_bounds__(256, 3) hop2_kernel(
    const float* __restrict__ x2,
    const float* __restrict__ lw, const float* __restrict__ lb,
    const float* __restrict__ iw, const float* __restrict__ ib,
    const float* __restrict__ ow, const float* __restrict__ ob) {
    extern __shared__ float sm[];
    const int tid = threadIdx.x;
    stage_weights(sm, tid, 256, lw, lb, iw, ib, ow, ob);
    __syncthreads();

    const int seq = tid >> 5, r = tid & 31;
    const long sg = (long)blockIdx.x * WPC + seq;
    float* buf = sm + 4960 + seq * BUFF;
    const float* xrow = x2 + (sg * 32 + r) * 30;

    float m = run_layer<32, true>(r, xrow, sm, buf, 1.f / 32.f);
    if (r < 30) g_h1[sg * 30 + r] = m;
}

// ===========================================================================
// hop1: 8 nodes/CTA + classifier MLP + 2-class softmax.
// ===========================================================================
#define OFF_CW1P 13408
#define OFF_CB1  (OFF_CW1P + 64 * 31)   // 15392
#define OFF_CW2P (OFF_CB1 + 64)         // 15456
#define OFF_CB2  (OFF_CW2P + 64 * 65)   // 19616
#define OFF_CW3  (OFF_CB2 + 64)         // 19680
#define OFF_CB3  (OFF_CW3 + 128)        // 19808
#define OFF_EMB  (OFF_CB3 + 4)          // 19812
#define OFF_HA   (OFF_EMB + 256)        // 20068
#define OFF_HB   (OFF_HA + 512)         // 20580
#define SMEM2_FLOATS (OFF_HB + 512)     // 21092 -> 84,368 B

__global__ void __launch_bounds__(256, 2) hop1_kernel(
    const float* __restrict__ self_feat,
    const float* __restrict__ lw, const float* __restrict__ lb,
    const float* __restrict__ iw, const float* __restrict__ ib,
    const float* __restrict__ ow, const float* __restrict__ ob,
    const float* __restrict__ cw1, const float* __restrict__ cb1,
    const float* __restrict__ cw2, const float* __restrict__ cb2,
    const float* __restrict__ cw3, const float* __restrict__ cb3,
    float* __restrict__ out) {
    extern __shared__ float sm[];
    const int tid = threadIdx.x;
    stage_weights(sm, tid, 256, lw, lb, iw, ib, ow, ob);
    float* cw1p = sm + OFF_CW1P;
    float* cb1s = sm + OFF_CB1;
    float* cw2p = sm + OFF_CW2P;
    float* cb2s = sm + OFF_CB2;
    float* cw3s = sm + OFF_CW3;
    float* cb3s = sm + OFF_CB3;
    float* embS = sm + OFF_EMB;
    float* hA   = sm + OFF_HA;
    float* hB   = sm + OFF_HB;
    for (int i = tid; i < 64 * 31; i += 256) {
        int row = i / 31, c = i % 31;
        cw1p[i] = (c < 30) ? cw1[row * 30 + c] : 0.f;
    }
    for (int i = tid; i < 64 * 65; i += 256) {
        int row = i / 65, c = i % 65;
        cw2p[i] = (c < 64) ? cw2[row * 64 + c] : 0.f;
    }
    if (tid < 64)  { cb1s[tid] = cb1[tid]; cb2s[tid] = cb2[tid]; }
    if (tid < 128) cw3s[tid] = cw3[tid];
    if (tid < 2)   cb3s[tid] = cb3[tid];
    __syncthreads();

    const int seq = tid >> 5, r = tid & 31;
    const int b = blockIdx.x * WPC + seq;
    float* buf = sm + 4960 + seq * BUFF;
    const float* xrow = (r < 16) ? (g_h1 + ((long)b * 16 + r) * 30)
                                 : (self_feat + (long)b * 30);

    float m = run_layer<17, false>(r, xrow, sm, buf, 1.f / 17.f);
    if (r < 30) embS[seq * 32 + r] = m;
    __syncwarp();

    // ---- classifier MLP (per warp) ----------------------------------------
    const float* emb = embS + seq * 32;
#pragma unroll
    for (int half = 0; half < 2; half++) {
        int j = r + 32 * half;
        float acc = cb1s[j];
#pragma unroll
        for (int k = 0; k < 30; k++) acc += emb[k] * cw1p[j * 31 + k];
        hA[seq * 64 + j] = fmaxf(acc, NEG * acc);
    }
    __syncwarp();
#pragma unroll
    for (int half = 0; half < 2; half++) {
        int j = r + 32 * half;
        float acc = cb2s[j];
#pragma unroll
        for (int k = 0; k < 64; k++) acc += hA[seq * 64 + k] * cw2p[j * 65 + k];
        hB[seq * 64 + j] = fmaxf(acc, NEG * acc);
    }
    __syncwarp();
    if (r < 2) {
        float acc = cb3s[r];
#pragma unroll
        for (int k = 0; k < 64; k++) acc += hB[seq * 64 + k] * cw3s[r * 64 + k];
        embS[seq * 32 + 30 + r] = acc;
    }
    __syncwarp();
    if (r == 0) {
        float l0 = embS[seq * 32 + 30], l1 = embS[seq * 32 + 31];
        float mx = fmaxf(l0, l1);
        float e0 = __expf(l0 - mx), e1 = __expf(l1 - mx);
        float inv = 1.f / (e0 + e1);
        out[(long)b * 2 + 0] = e0 * inv;
        out[(long)b * 2 + 1] = e1 * inv;
    }
}

// ===========================================================================
extern "C" void kernel_launch(void* const* d_in, const int* in_sizes, int n_in,
                              void* d_out, int out_size) {
    const float* x2   = (const float*)d_in[0];
    const float* self = (const float*)d_in[1];
    const float* lw2  = (const float*)d_in[2];
    const float* lb2  = (const float*)d_in[3];
    const float* iw2  = (const float*)d_in[4];
    const float* ib2  = (const float*)d_in[5];
    const float* ow2  = (const float*)d_in[6];
    const float* ob2  = (const float*)d_in[7];
    const float* lw1  = (const float*)d_in[8];
    const float* lb1  = (const float*)d_in[9];
    const float* iw1  = (const float*)d_in[10];
    const float* ib1  = (const float*)d_in[11];
    const float* ow1  = (const float*)d_in[12];
    const float* ob1  = (const float*)d_in[13];
    const float* cw1  = (const float*)d_in[14];
    const float* cb1  = (const float*)d_in[15];
    const float* cw2  = (const float*)d_in[16];
    const float* cb2  = (const float*)d_in[17];
    const float* cw3  = (const float*)d_in[18];
    const float* cb3  = (const float*)d_in[19];
    float* out = (float*)d_out;

    const int smem1 = SMEM1_FLOATS * 4;
    const int smem2 = SMEM2_FLOATS * 4;
    cudaFuncSetAttribute(hop2_kernel,
                         cudaFuncAttributeMaxDynamicSharedMemorySize, smem1);
    cudaFuncSetAttribute(hop1_kernel,
                         cudaFuncAttributeMaxDynamicSharedMemorySize, smem2);

    hop2_kernel<<<(NB * 16) / WPC, 256, smem1>>>(x2, lw2, lb2, iw2, ib2, ow2, ob2);
    hop1_kernel<<<NB / WPC, 256, smem2>>>(self, lw1, lb1, iw1, ib1, ow1, ob1,
                                          cw1, cb1, cw2, cb2, cw3, cb3, out);
}

// round 5
// speedup vs baseline: 1.6616x; 1.4338x over previous
#include <cuda_runtime.h>

#define NB 4096
#define NEG 0.02f
// (1/sqrt(5)) * log2(e)
#define CEXP 0.6451928329f

typedef unsigned long long u64;

// hop-2 output: [B*N1, 30]
__device__ float g_h1[NB * 16 * 30];

// ---------------------------------------------------------------------------
__device__ __forceinline__ u64 pk2(float lo, float hi) {
    u64 v; asm("mov.b64 %0,{%1,%2};" : "=l"(v) : "f"(lo), "f"(hi)); return v;
}
__device__ __forceinline__ float2 upk2(u64 v) {
    float2 r; asm("mov.b64 {%0,%1},%2;" : "=f"(r.x), "=f"(r.y) : "l"(v)); return r;
}
__device__ __forceinline__ u64 f2fma(u64 a, u64 b, u64 c) {
    u64 d; asm("fma.rn.f32x2 %0,%1,%2,%3;" : "=l"(d) : "l"(a), "l"(b), "l"(c));
    return d;
}
__device__ __forceinline__ float ex2f(float x) {
    float r; asm("ex2.approx.f32 %0,%1;" : "=f"(r) : "f"(x)); return r;
}
__device__ __forceinline__ float rcpf(float x) {
    float r; asm("rcp.approx.f32 %0,%1;" : "=f"(r) : "f"(x)); return r;
}

// packed dot: 32-float weight row (pad zeroed) vs 16 packed f32x2 regs
__device__ __forceinline__ float dotp(const float* __restrict__ wrow,
                                      const u64 (&v)[16]) {
    const ulonglong2* w2 = (const ulonglong2*)wrow;
    u64 a0 = 0ull, a1 = 0ull;
#pragma unroll
    for (int kk = 0; kk < 4; kk++) {
        ulonglong2 wa = w2[2 * kk];
        ulonglong2 wb = w2[2 * kk + 1];
        a0 = f2fma(wa.x, v[4 * kk + 0], a0);
        a1 = f2fma(wa.y, v[4 * kk + 1], a1);
        a0 = f2fma(wb.x, v[4 * kk + 2], a0);
        a1 = f2fma(wb.y, v[4 * kk + 3], a1);
    }
    float2 x = upk2(a0), y = upk2(a1);
    return (x.x + x.y) + (y.x + y.y);
}

// ---------------------------------------------------------------------------
// Per-seq scratch buffer (floats). Layout (head-group of 3 heads):
//   KA : ulonglong2[96]  [0,384)    (k0,k1,k2,k3) per (head j, row t)
//   KT : float[96]       [384,480)  k4
//   VA : ulonglong2[96]  [480,864)
//   VT : u64[96]         [864,1056) (v4, 1.0)
//   red: float[S][33]    [0,1056)   reused after attention
// ---------------------------------------------------------------------------
#define BUFF 1056

// sm layout: lw 0..959 | iw 960..3839 | owT 3840..4799 | lb 4800 | ib 4832 |
//            ob 4928..4959   (owT is TRANSPOSED: owT[c][j] = ow[j][c])
template <int S, bool FULL>
__device__ __forceinline__ float run_layer(int r,
                                           const float* __restrict__ xrow,
                                           const float* __restrict__ sm,
                                           float* __restrict__ buf,
                                           float invS) {
    const float* lw_s  = sm;
    const float* iw_s  = sm + 960;
    const float* owT_s = sm + 3840;
    const float* lb_s  = sm + 4800;
    const float* ib_s  = sm + 4832;
    const float* ob_s  = sm + 4928;
    const bool act = FULL || (r < S);

    ulonglong2* KA = (ulonglong2*)buf;
    float*      KT = buf + 384;
    ulonglong2* VA = (ulonglong2*)(buf + 480);
    u64*        VT = (u64*)(buf + 864);

    // ---- stage 1: y = leaky(x @ lw^T + lb), kept packed -------------------
    u64 yp[16];
    if (act) {
        u64 xp[16];
#pragma unroll
        for (int k = 0; k < 15; k++) {
            float2 t = *(const float2*)(xrow + 2 * k);
            xp[k] = pk2(t.x, t.y);
        }
        xp[15] = 0ull;
#pragma unroll
        for (int jj = 0; jj < 15; jj++) {
            float y0 = lb_s[2 * jj]     + dotp(lw_s + (2 * jj) * 32, xp);
            float y1 = lb_s[2 * jj + 1] + dotp(lw_s + (2 * jj + 1) * 32, xp);
            y0 = fmaxf(y0, NEG * y0);
            y1 = fmaxf(y1, NEG * y1);
            yp[jj] = pk2(y0, y1);
        }
        yp[15] = 0ull;
    }

    // out-proj accumulator, packed over output pairs; init with bias
    u64 red2[15];
    {
        const u64* obp = (const u64*)ob_s;
#pragma unroll
        for (int p = 0; p < 15; p++) red2[p] = obp[p];
    }

    // ---- head groups of 3: qkv -> stage -> attention + partial out-proj ---
#pragma unroll 1
    for (int g = 0; g < 2; g++) {
        u64 q01[3], q23[3];
        float q4[3];
        if (act) {
#pragma unroll
            for (int j = 0; j < 3; j++) {
                const int h = g * 3 + j;
                float a0 = (ib_s[h * 5 + 0] + dotp(iw_s + (h * 5 + 0) * 32, yp)) * CEXP;
                float a1 = (ib_s[h * 5 + 1] + dotp(iw_s + (h * 5 + 1) * 32, yp)) * CEXP;
                float a2 = (ib_s[h * 5 + 2] + dotp(iw_s + (h * 5 + 2) * 32, yp)) * CEXP;
                float a3 = (ib_s[h * 5 + 3] + dotp(iw_s + (h * 5 + 3) * 32, yp)) * CEXP;
                float a4 = (ib_s[h * 5 + 4] + dotp(iw_s + (h * 5 + 4) * 32, yp)) * CEXP;
                q01[j] = pk2(a0, a1); q23[j] = pk2(a2, a3); q4[j] = a4;

                float k0 = ib_s[30 + h * 5 + 0] + dotp(iw_s + (30 + h * 5 + 0) * 32, yp);
                float k1 = ib_s[30 + h * 5 + 1] + dotp(iw_s + (30 + h * 5 + 1) * 32, yp);
                float k2 = ib_s[30 + h * 5 + 2] + dotp(iw_s + (30 + h * 5 + 2) * 32, yp);
                float k3 = ib_s[30 + h * 5 + 3] + dotp(iw_s + (30 + h * 5 + 3) * 32, yp);
                float k4 = ib_s[30 + h * 5 + 4] + dotp(iw_s + (30 + h * 5 + 4) * 32, yp);
                float v0 = ib_s[60 + h * 5 + 0] + dotp(iw_s + (60 + h * 5 + 0) * 32, yp);
                float v1 = ib_s[60 + h * 5 + 1] + dotp(iw_s + (60 + h * 5 + 1) * 32, yp);
                float v2 = ib_s[60 + h * 5 + 2] + dotp(iw_s + (60 + h * 5 + 2) * 32, yp);
                float v3 = ib_s[60 + h * 5 + 3] + dotp(iw_s + (60 + h * 5 + 3) * 32, yp);
                float v4 = ib_s[60 + h * 5 + 4] + dotp(iw_s + (60 + h * 5 + 4) * 32, yp);

                ulonglong2 kk; kk.x = pk2(k0, k1); kk.y = pk2(k2, k3);
                KA[j * 32 + r] = kk;
                KT[j * 32 + r] = k4;
                ulonglong2 vv; vv.x = pk2(v0, v1); vv.y = pk2(v2, v3);
                VA[j * 32 + r] = vv;
                VT[j * 32 + r] = pk2(v4, 1.0f);
            }
        }
        __syncwarp();
        if (act) {
#pragma unroll
            for (int j = 0; j < 3; j++) {
                const int h = g * 3 + j;
                u64 a01 = 0ull, a23 = 0ull, a4s = 0ull;
#pragma unroll 4
                for (int t = 0; t < S; t++) {
                    ulonglong2 ka = KA[j * 32 + t];
                    float k4v = KT[j * 32 + t];
                    u64 s2 = f2fma(ka.x, q01[j], f2fma(ka.y, q23[j], 0ull));
                    float2 sp = upk2(s2);
                    float e = ex2f(fmaf(q4[j], k4v, sp.x + sp.y));
                    u64 ee = pk2(e, e);
                    ulonglong2 va = VA[j * 32 + t];
                    a01 = f2fma(ee, va.x, a01);
                    a23 = f2fma(ee, va.y, a23);
                    a4s = f2fma(ee, VT[j * 32 + t], a4s);
                }
                float2 s4 = upk2(a4s);              // (sum e*v4, sum e)
                float inv = rcpf(s4.y);
                float2 p01 = upk2(a01), p23 = upk2(a23);
                float od[5];
                od[0] = p01.x * inv; od[1] = p01.y * inv;
                od[2] = p23.x * inv; od[3] = p23.y * inv;
                od[4] = s4.x * inv;
                // partial transposed out-proj: red2 += od[d] * owT[h*5+d][:]
#pragma unroll
                for (int d = 0; d < 5; d++) {
                    const u64* w = (const u64*)(owT_s + (h * 5 + d) * 32);
                    u64 o2 = pk2(od[d], od[d]);
#pragma unroll
                    for (int p = 0; p < 15; p++)
                        red2[p] = f2fma(w[p], o2, red2[p]);
                }
            }
        }
        __syncwarp();
    }

    // ---- write per-row out, then column mean ------------------------------
    float* red = buf;   // [S][33], overlaps K/V (synced above)
    if (act) {
#pragma unroll
        for (int p = 0; p < 15; p++) {
            float2 v = upk2(red2[p]);
            red[r * 33 + 2 * p]     = v.x;
            red[r * 33 + 2 * p + 1] = v.y;
        }
    }
    __syncwarp();
    float mean = 0.f;
    if (r < 30) {
#pragma unroll
        for (int t = 0; t < S; t++) mean += red[t * 33 + r];
        mean *= invS;
    }
    return mean;
}

// ---------------------------------------------------------------------------
__device__ __forceinline__ void stage_weights(float* sm, int tid, int nthr,
                                              const float* lw, const float* lb,
                                              const float* iw, const float* ib,
                                              const float* ow, const float* ob) {
    for (int i = tid; i < 4800; i += nthr) {
        int row = i >> 5, col = i & 31;
        float v = 0.f;
        if (col < 30) {
            if (row < 30)       v = lw[row * 30 + col];
            else if (row < 120) v = iw[(row - 30) * 30 + col];
            else                v = ow[col * 30 + (row - 120)];   // transposed
        }
        sm[i] = v;
    }
    if (tid < 30) sm[4800 + tid] = lb[tid];
    if (tid < 90) sm[4832 + tid] = ib[tid];
    if (tid < 32) sm[4928 + tid] = (tid < 30) ? ob[tid] : 0.f;
}

// ===========================================================================
// hop2: 8 sequences/CTA (one per warp), 65536 sequences total.
// ===========================================================================
#define WPC 8
#define SMEM1_FLOATS (4960 + WPC * BUFF)    // 13408 -> 53,632 B

__global__ void __launch_bounds__(256, 3) hop2_kernel(
    const float* __restrict__ x2,
    const float* __restrict__ lw, const float* __restrict__ lb,
    const float* __restrict__ iw, const float* __restrict__ ib,
    const float* __restrict__ ow, const float* __restrict__ ob) {
    extern __shared__ float sm[];
    const int tid = threadIdx.x;
    stage_weights(sm, tid, 256, lw, lb, iw, ib, ow, ob);
    __syncthreads();

    const int seq = tid >> 5, r = tid & 31;
    const long sg = (long)blockIdx.x * WPC + seq;
    float* buf = sm + 4960 + seq * BUFF;
    const float* xrow = x2 + (sg * 32 + r) * 30;

    float m = run_layer<32, true>(r, xrow, sm, buf, 1.f / 32.f);
    if (r < 30) g_h1[sg * 30 + r] = m;
}

// ===========================================================================
// hop1: 8 nodes/CTA + classifier MLP + 2-class softmax.
// ===========================================================================
#define OFF_CW1P 13408
#define OFF_CB1  (OFF_CW1P + 64 * 31)   // 15392
#define OFF_CW2P (OFF_CB1 + 64)         // 15456
#define OFF_CB2  (OFF_CW2P + 64 * 65)   // 19616
#define OFF_CW3  (OFF_CB2 + 64)         // 19680
#define OFF_CB3  (OFF_CW3 + 128)        // 19808
#define OFF_EMB  (OFF_CB3 + 4)          // 19812
#define OFF_HA   (OFF_EMB + 256)        // 20068
#define OFF_HB   (OFF_HA + 512)         // 20580
#define SMEM2_FLOATS (OFF_HB + 512)     // 21092 -> 84,368 B

__global__ void __launch_bounds__(256, 2) hop1_kernel(
    const float* __restrict__ self_feat,
    const float* __restrict__ lw, const float* __restrict__ lb,
    const float* __restrict__ iw, const float* __restrict__ ib,
    const float* __restrict__ ow, const float* __restrict__ ob,
    const float* __restrict__ cw1, const float* __restrict__ cb1,
    const float* __restrict__ cw2, const float* __restrict__ cb2,
    const float* __restrict__ cw3, const float* __restrict__ cb3,
    float* __restrict__ out) {
    extern __shared__ float sm[];
    const int tid = threadIdx.x;
    stage_weights(sm, tid, 256, lw, lb, iw, ib, ow, ob);
    float* cw1p = sm + OFF_CW1P;
    float* cb1s = sm + OFF_CB1;
    float* cw2p = sm + OFF_CW2P;
    float* cb2s = sm + OFF_CB2;
    float* cw3s = sm + OFF_CW3;
    float* cb3s = sm + OFF_CB3;
    float* embS = sm + OFF_EMB;
    float* hA   = sm + OFF_HA;
    float* hB   = sm + OFF_HB;
    for (int i = tid; i < 64 * 31; i += 256) {
        int row = i / 31, c = i % 31;
        cw1p[i] = (c < 30) ? cw1[row * 30 + c] : 0.f;
    }
    for (int i = tid; i < 64 * 65; i += 256) {
        int row = i / 65, c = i % 65;
        cw2p[i] = (c < 64) ? cw2[row * 64 + c] : 0.f;
    }
    if (tid < 64)  { cb1s[tid] = cb1[tid]; cb2s[tid] = cb2[tid]; }
    if (tid < 128) cw3s[tid] = cw3[tid];
    if (tid < 2)   cb3s[tid] = cb3[tid];
    __syncthreads();

    const int seq = tid >> 5, r = tid & 31;
    const int b = blockIdx.x * WPC + seq;
    float* buf = sm + 4960 + seq * BUFF;
    const float* xrow = (r < 16) ? (g_h1 + ((long)b * 16 + r) * 30)
                                 : (self_feat + (long)b * 30);

    float m = run_layer<17, false>(r, xrow, sm, buf, 1.f / 17.f);
    if (r < 30) embS[seq * 32 + r] = m;
    __syncwarp();

    // ---- classifier MLP (per warp) ----------------------------------------
    const float* emb = embS + seq * 32;
#pragma unroll
    for (int half = 0; half < 2; half++) {
        int j = r + 32 * half;
        float acc = cb1s[j];
#pragma unroll
        for (int k = 0; k < 30; k++) acc += emb[k] * cw1p[j * 31 + k];
        hA[seq * 64 + j] = fmaxf(acc, NEG * acc);
    }
    __syncwarp();
#pragma unroll
    for (int half = 0; half < 2; half++) {
        int j = r + 32 * half;
        float acc = cb2s[j];
#pragma unroll
        for (int k = 0; k < 64; k++) acc += hA[seq * 64 + k] * cw2p[j * 65 + k];
        hB[seq * 64 + j] = fmaxf(acc, NEG * acc);
    }
    __syncwarp();
    if (r < 2) {
        float acc = cb3s[r];
#pragma unroll
        for (int k = 0; k < 64; k++) acc += hB[seq * 64 + k] * cw3s[r * 64 + k];
        embS[seq * 32 + 30 + r] = acc;
    }
    __syncwarp();
    if (r == 0) {
        float l0 = embS[seq * 32 + 30], l1 = embS[seq * 32 + 31];
        float mx = fmaxf(l0, l1);
        float e0 = __expf(l0 - mx), e1 = __expf(l1 - mx);
        float inv = 1.f / (e0 + e1);
        out[(long)b * 2 + 0] = e0 * inv;
        out[(long)b * 2 + 1] = e1 * inv;
    }
}

// ===========================================================================
extern "C" void kernel_launch(void* const* d_in, const int* in_sizes, int n_in,
                              void* d_out, int out_size) {
    const float* x2   = (const float*)d_in[0];
    const float* self = (const float*)d_in[1];
    const float* lw2  = (const float*)d_in[2];
    const float* lb2  = (const float*)d_in[3];
    const float* iw2  = (const float*)d_in[4];
    const float* ib2  = (const float*)d_in[5];
    const float* ow2  = (const float*)d_in[6];
    const float* ob2  = (const float*)d_in[7];
    const float* lw1  = (const float*)d_in[8];
    const float* lb1  = (const float*)d_in[9];
    const float* iw1  = (const float*)d_in[10];
    const float* ib1  = (const float*)d_in[11];
    const float* ow1  = (const float*)d_in[12];
    const float* ob1  = (const float*)d_in[13];
    const float* cw1  = (const float*)d_in[14];
    const float* cb1  = (const float*)d_in[15];
    const float* cw2  = (const float*)d_in[16];
    const float* cb2  = (const float*)d_in[17];
    const float* cw3  = (const float*)d_in[18];
    const float* cb3  = (const float*)d_in[19];
    float* out = (float*)d_out;

    const int smem1 = SMEM1_FLOATS * 4;
    const int smem2 = SMEM2_FLOATS * 4;
    cudaFuncSetAttribute(hop2_kernel,
                         cudaFuncAttributeMaxDynamicSharedMemorySize, smem1);
    cudaFuncSetAttribute(hop1_kernel,
                         cudaFuncAttributeMaxDynamicSharedMemorySize, smem2);

    hop2_kernel<<<(NB * 16) / WPC, 256, smem1>>>(x2, lw2, lb2, iw2, ib2, ow2, ob2);
    hop1_kernel<<<NB / WPC, 256, smem2>>>(self, lw1, lb1, iw1, ib1, ow1, ob1,
                                          cw1, cb1, cw2, cb2, cw3, cb3, out);
}

// round 6
// speedup vs baseline: 1.8643x; 1.1220x over previous
#include <cuda_runtime.h>

#define NB 4096
#define NEG 0.02f
// (1/sqrt(5)) * log2(e)
#define CEXP 0.6451928329f

typedef unsigned long long u64;

// hop-2 output: [B*N1, 30]
__device__ float g_h1[NB * 16 * 30];

// ---------------------------------------------------------------------------
__device__ __forceinline__ u64 pk2(float lo, float hi) {
    u64 v; asm("mov.b64 %0,{%1,%2};" : "=l"(v) : "f"(lo), "f"(hi)); return v;
}
__device__ __forceinline__ float2 upk2(u64 v) {
    float2 r; asm("mov.b64 {%0,%1},%2;" : "=f"(r.x), "=f"(r.y) : "l"(v)); return r;
}
__device__ __forceinline__ u64 f2fma(u64 a, u64 b, u64 c) {
    u64 d; asm("fma.rn.f32x2 %0,%1,%2,%3;" : "=l"(d) : "l"(a), "l"(b), "l"(c));
    return d;
}
__device__ __forceinline__ u64 f2add(u64 a, u64 b) {
    u64 d; asm("add.rn.f32x2 %0,%1,%2;" : "=l"(d) : "l"(a), "l"(b));
    return d;
}
__device__ __forceinline__ float ex2f(float x) {
    float r; asm("ex2.approx.f32 %0,%1;" : "=f"(r) : "f"(x)); return r;
}
__device__ __forceinline__ float rcpf(float x) {
    float r; asm("rcp.approx.f32 %0,%1;" : "=f"(r) : "f"(x)); return r;
}

// packed dot, 4 accumulators (chain depth 2): 32-float weight row vs 16 u64
__device__ __forceinline__ float dotp(const float* __restrict__ wrow,
                                      const u64 (&v)[16]) {
    const ulonglong2* w2 = (const ulonglong2*)wrow;
    u64 a0 = 0ull, a1 = 0ull, a2 = 0ull, a3 = 0ull;
#pragma unroll
    for (int kk = 0; kk < 2; kk++) {
        ulonglong2 wa = w2[4 * kk + 0];
        ulonglong2 wb = w2[4 * kk + 1];
        ulonglong2 wc = w2[4 * kk + 2];
        ulonglong2 wd = w2[4 * kk + 3];
        a0 = f2fma(wa.x, v[8 * kk + 0], a0);
        a1 = f2fma(wa.y, v[8 * kk + 1], a1);
        a2 = f2fma(wb.x, v[8 * kk + 2], a2);
        a3 = f2fma(wb.y, v[8 * kk + 3], a3);
        a0 = f2fma(wc.x, v[8 * kk + 4], a0);
        a1 = f2fma(wc.y, v[8 * kk + 5], a1);
        a2 = f2fma(wd.x, v[8 * kk + 6], a2);
        a3 = f2fma(wd.y, v[8 * kk + 7], a3);
    }
    u64 s = f2add(f2add(a0, a1), f2add(a2, a3));
    float2 f = upk2(s);
    return f.x + f.y;
}

// ---------------------------------------------------------------------------
// Per-seq scratch buffer (floats). Layout (head-group of 3 heads):
//   KA : ulonglong2[96]  [0,384)    (k0,k1,k2,k3) per (head j, row t)
//   KT : float[96]       [384,480)  k4
//   VA : ulonglong2[96]  [480,864)
//   VT : u64[96]         [864,1056) (v4, 1.0)
//   red: float[S][33]    [0,1056)   reused after attention
// ---------------------------------------------------------------------------
#define BUFF 1056

// sm layout: lw 0..959 | iw 960..3839 | owT 3840..4799 | lb 4800 | ib 4832 |
//            ob 4928..4959   (owT TRANSPOSED; q-rows of iw and q-bias
//            pre-scaled by CEXP at staging time)
template <int S, bool FULL>
__device__ __forceinline__ float run_layer(int r,
                                           const float* __restrict__ xrow,
                                           const float* __restrict__ sm,
                                           float* __restrict__ buf,
                                           float invS) {
    const float* lw_s  = sm;
    const float* iw_s  = sm + 960;
    const float* owT_s = sm + 3840;
    const float* lb_s  = sm + 4800;
    const float* ib_s  = sm + 4832;
    const float* ob_s  = sm + 4928;
    const bool act = FULL || (r < S);

    ulonglong2* KA = (ulonglong2*)buf;
    float*      KT = buf + 384;
    ulonglong2* VA = (ulonglong2*)(buf + 480);
    u64*        VT = (u64*)(buf + 864);

    // ---- stage 1: y = leaky(x @ lw^T + lb), kept packed -------------------
    u64 yp[16];
    if (act) {
        u64 xp[16];
#pragma unroll
        for (int k = 0; k < 15; k++) {
            float2 t = *(const float2*)(xrow + 2 * k);
            xp[k] = pk2(t.x, t.y);
        }
        xp[15] = 0ull;
#pragma unroll
        for (int jj = 0; jj < 15; jj++) {
            float y0 = lb_s[2 * jj]     + dotp(lw_s + (2 * jj) * 32, xp);
            float y1 = lb_s[2 * jj + 1] + dotp(lw_s + (2 * jj + 1) * 32, xp);
            y0 = fmaxf(y0, NEG * y0);
            y1 = fmaxf(y1, NEG * y1);
            yp[jj] = pk2(y0, y1);
        }
        yp[15] = 0ull;
    }

    // out-proj accumulator, packed over output pairs; init with bias
    u64 red2[15];
    {
        const u64* obp = (const u64*)ob_s;
#pragma unroll
        for (int p = 0; p < 15; p++) red2[p] = obp[p];
    }

    // ---- head groups of 3: qkv -> stage -> attention + partial out-proj ---
#pragma unroll 1
    for (int g = 0; g < 2; g++) {
        u64 q01[3], q23[3];
        float q4[3];
        if (act) {
#pragma unroll
            for (int j = 0; j < 3; j++) {
                const int h = g * 3 + j;
                // q rows/bias pre-scaled by CEXP during staging
                float a0 = ib_s[h * 5 + 0] + dotp(iw_s + (h * 5 + 0) * 32, yp);
                float a1 = ib_s[h * 5 + 1] + dotp(iw_s + (h * 5 + 1) * 32, yp);
                float a2 = ib_s[h * 5 + 2] + dotp(iw_s + (h * 5 + 2) * 32, yp);
                float a3 = ib_s[h * 5 + 3] + dotp(iw_s + (h * 5 + 3) * 32, yp);
                float a4 = ib_s[h * 5 + 4] + dotp(iw_s + (h * 5 + 4) * 32, yp);
                q01[j] = pk2(a0, a1); q23[j] = pk2(a2, a3); q4[j] = a4;

                float k0 = ib_s[30 + h * 5 + 0] + dotp(iw_s + (30 + h * 5 + 0) * 32, yp);
                float k1 = ib_s[30 + h * 5 + 1] + dotp(iw_s + (30 + h * 5 + 1) * 32, yp);
                float k2 = ib_s[30 + h * 5 + 2] + dotp(iw_s + (30 + h * 5 + 2) * 32, yp);
                float k3 = ib_s[30 + h * 5 + 3] + dotp(iw_s + (30 + h * 5 + 3) * 32, yp);
                float k4 = ib_s[30 + h * 5 + 4] + dotp(iw_s + (30 + h * 5 + 4) * 32, yp);
                float v0 = ib_s[60 + h * 5 + 0] + dotp(iw_s + (60 + h * 5 + 0) * 32, yp);
                float v1 = ib_s[60 + h * 5 + 1] + dotp(iw_s + (60 + h * 5 + 1) * 32, yp);
                float v2 = ib_s[60 + h * 5 + 2] + dotp(iw_s + (60 + h * 5 + 2) * 32, yp);
                float v3 = ib_s[60 + h * 5 + 3] + dotp(iw_s + (60 + h * 5 + 3) * 32, yp);
                float v4 = ib_s[60 + h * 5 + 4] + dotp(iw_s + (60 + h * 5 + 4) * 32, yp);

                ulonglong2 kk; kk.x = pk2(k0, k1); kk.y = pk2(k2, k3);
                KA[j * 32 + r] = kk;
                KT[j * 32 + r] = k4;
                ulonglong2 vv; vv.x = pk2(v0, v1); vv.y = pk2(v2, v3);
                VA[j * 32 + r] = vv;
                VT[j * 32 + r] = pk2(v4, 1.0f);
            }
        }
        __syncwarp();
        if (act) {
#pragma unroll
            for (int j = 0; j < 3; j++) {
                const int h = g * 3 + j;
                u64 a01 = 0ull, a23 = 0ull, a4s = 0ull;
#pragma unroll 8
                for (int t = 0; t < S; t++) {
                    ulonglong2 ka = KA[j * 32 + t];
                    float k4v = KT[j * 32 + t];
                    u64 s2 = f2fma(ka.x, q01[j], f2fma(ka.y, q23[j], 0ull));
                    float2 sp = upk2(s2);
                    float e = ex2f(fmaf(q4[j], k4v, sp.x + sp.y));
                    u64 ee = pk2(e, e);
                    ulonglong2 va = VA[j * 32 + t];
                    a01 = f2fma(ee, va.x, a01);
                    a23 = f2fma(ee, va.y, a23);
                    a4s = f2fma(ee, VT[j * 32 + t], a4s);
                }
                float2 s4 = upk2(a4s);              // (sum e*v4, sum e)
                float inv = rcpf(s4.y);
                float2 p01 = upk2(a01), p23 = upk2(a23);
                float od[5];
                od[0] = p01.x * inv; od[1] = p01.y * inv;
                od[2] = p23.x * inv; od[3] = p23.y * inv;
                od[4] = s4.x * inv;
                // partial transposed out-proj: red2 += od[d] * owT[h*5+d][:]
#pragma unroll
                for (int d = 0; d < 5; d++) {
                    const u64* w = (const u64*)(owT_s + (h * 5 + d) * 32);
                    u64 o2 = pk2(od[d], od[d]);
#pragma unroll
                    for (int p = 0; p < 15; p++)
                        red2[p] = f2fma(w[p], o2, red2[p]);
                }
            }
        }
        __syncwarp();
    }

    // ---- write per-row out, then column mean ------------------------------
    float* red = buf;   // [S][33], overlaps K/V (synced above)
    if (act) {
#pragma unroll
        for (int p = 0; p < 15; p++) {
            float2 v = upk2(red2[p]);
            red[r * 33 + 2 * p]     = v.x;
            red[r * 33 + 2 * p + 1] = v.y;
        }
    }
    __syncwarp();
    float mean = 0.f;
    if (r < 30) {
#pragma unroll
        for (int t = 0; t < S; t++) mean += red[t * 33 + r];
        mean *= invS;
    }
    return mean;
}

// ---------------------------------------------------------------------------
__device__ __forceinline__ void stage_weights(float* sm, int tid, int nthr,
                                              const float* lw, const float* lb,
                                              const float* iw, const float* ib,
                                              const float* ow, const float* ob) {
    for (int i = tid; i < 4800; i += nthr) {
        int row = i >> 5, col = i & 31;
        float v = 0.f;
        if (col < 30) {
            if (row < 30)       v = lw[row * 30 + col];
            else if (row < 120) {
                v = iw[(row - 30) * 30 + col];
                if (row < 60) v *= CEXP;            // fold attn scale into q
            } else                v = ow[col * 30 + (row - 120)];   // transposed
        }
        sm[i] = v;
    }
    if (tid < 30) sm[4800 + tid] = lb[tid];
    if (tid < 90) sm[4832 + tid] = (tid < 30) ? ib[tid] * CEXP : ib[tid];
    if (tid < 32) sm[4928 + tid] = (tid < 30) ? ob[tid] : 0.f;
}

// ===========================================================================
// hop2: 8 sequences/CTA (one per warp), 65536 sequences total.
// ===========================================================================
#define WPC 8
#define SMEM1_FLOATS (4960 + WPC * BUFF)    // 13408 -> 53,632 B

__global__ void __launch_bounds__(256, 2) hop2_kernel(
    const float* __restrict__ x2,
    const float* __restrict__ lw, const float* __restrict__ lb,
    const float* __restrict__ iw, const float* __restrict__ ib,
    const float* __restrict__ ow, const float* __restrict__ ob) {
    extern __shared__ float sm[];
    const int tid = threadIdx.x;
    stage_weights(sm, tid, 256, lw, lb, iw, ib, ow, ob);
    __syncthreads();

    const int seq = tid >> 5, r = tid & 31;
    const long sg = (long)blockIdx.x * WPC + seq;
    float* buf = sm + 4960 + seq * BUFF;
    const float* xrow = x2 + (sg * 32 + r) * 30;

    float m = run_layer<32, true>(r, xrow, sm, buf, 1.f / 32.f);
    if (r < 30) g_h1[sg * 30 + r] = m;
}

// ===========================================================================
// hop1: 8 nodes/CTA + classifier MLP + 2-class softmax.
// ===========================================================================
#define OFF_CW1P 13408
#define OFF_CB1  (OFF_CW1P + 64 * 31)   // 15392
#define OFF_CW2P (OFF_CB1 + 64)         // 15456
#define OFF_CB2  (OFF_CW2P + 64 * 65)   // 19616
#define OFF_CW3  (OFF_CB2 + 64)         // 19680
#define OFF_CB3  (OFF_CW3 + 128)        // 19808
#define OFF_EMB  (OFF_CB3 + 4)          // 19812
#define OFF_HA   (OFF_EMB + 256)        // 20068
#define OFF_HB   (OFF_HA + 512)         // 20580
#define SMEM2_FLOATS (OFF_HB + 512)     // 21092 -> 84,368 B

__global__ void __launch_bounds__(256, 2) hop1_kernel(
    const float* __restrict__ self_feat,
    const float* __restrict__ lw, const float* __restrict__ lb,
    const float* __restrict__ iw, const float* __restrict__ ib,
    const float* __restrict__ ow, const float* __restrict__ ob,
    const float* __restrict__ cw1, const float* __restrict__ cb1,
    const float* __restrict__ cw2, const float* __restrict__ cb2,
    const float* __restrict__ cw3, const float* __restrict__ cb3,
    float* __restrict__ out) {
    extern __shared__ float sm[];
    const int tid = threadIdx.x;
    stage_weights(sm, tid, 256, lw, lb, iw, ib, ow, ob);
    float* cw1p = sm + OFF_CW1P;
    float* cb1s = sm + OFF_CB1;
    float* cw2p = sm + OFF_CW2P;
    float* cb2s = sm + OFF_CB2;
    float* cw3s = sm + OFF_CW3;
    float* cb3s = sm + OFF_CB3;
    float* embS = sm + OFF_EMB;
    float* hA   = sm + OFF_HA;
    float* hB   = sm + OFF_HB;
    for (int i = tid; i < 64 * 31; i += 256) {
        int row = i / 31, c = i % 31;
        cw1p[i] = (c < 30) ? cw1[row * 30 + c] : 0.f;
    }
    for (int i = tid; i < 64 * 65; i += 256) {
        int row = i / 65, c = i % 65;
        cw2p[i] = (c < 64) ? cw2[row * 64 + c] : 0.f;
    }
    if (tid < 64)  { cb1s[tid] = cb1[tid]; cb2s[tid] = cb2[tid]; }
    if (tid < 128) cw3s[tid] = cw3[tid];
    if (tid < 2)   cb3s[tid] = cb3[tid];
    __syncthreads();

    const int seq = tid >> 5, r = tid & 31;
    const int b = blockIdx.x * WPC + seq;
    float* buf = sm + 4960 + seq * BUFF;
    const float* xrow = (r < 16) ? (g_h1 + ((long)b * 16 + r) * 30)
                                 : (self_feat + (long)b * 30);

    float m = run_layer<17, false>(r, xrow, sm, buf, 1.f / 17.f);
    if (r < 30) embS[seq * 32 + r] = m;
    __syncwarp();

    // ---- classifier MLP (per warp) ----------------------------------------
    const float* emb = embS + seq * 32;
#pragma unroll
    for (int half = 0; half < 2; half++) {
        int j = r + 32 * half;
        float acc = cb1s[j];
#pragma unroll
        for (int k = 0; k < 30; k++) acc += emb[k] * cw1p[j * 31 + k];
        hA[seq * 64 + j] = fmaxf(acc, NEG * acc);
    }
    __syncwarp();
#pragma unroll
    for (int half = 0; half < 2; half++) {
        int j = r + 32 * half;
        float acc = cb2s[j];
#pragma unroll
        for (int k = 0; k < 64; k++) acc += hA[seq * 64 + k] * cw2p[j * 65 + k];
        hB[seq * 64 + j] = fmaxf(acc, NEG * acc);
    }
    __syncwarp();
    if (r < 2) {
        float acc = cb3s[r];
#pragma unroll
        for (int k = 0; k < 64; k++) acc += hB[seq * 64 + k] * cw3s[r * 64 + k];
        embS[seq * 32 + 30 + r] = acc;
    }
    __syncwarp();
    if (r == 0) {
        float l0 = embS[seq * 32 + 30], l1 = embS[seq * 32 + 31];
        float mx = fmaxf(l0, l1);
        float e0 = __expf(l0 - mx), e1 = __expf(l1 - mx);
        float inv = 1.f / (e0 + e1);
        out[(long)b * 2 + 0] = e0 * inv;
        out[(long)b * 2 + 1] = e1 * inv;
    }
}

// ===========================================================================
extern "C" void kernel_launch(void* const* d_in, const int* in_sizes, int n_in,
                              void* d_out, int out_size) {
    const float* x2   = (const float*)d_in[0];
    const float* self = (const float*)d_in[1];
    const float* lw2  = (const float*)d_in[2];
    const float* lb2  = (const float*)d_in[3];
    const float* iw2  = (const float*)d_in[4];
    const float* ib2  = (const float*)d_in[5];
    const float* ow2  = (const float*)d_in[6];
    const float* ob2  = (const float*)d_in[7];
    const float* lw1  = (const float*)d_in[8];
    const float* lb1  = (const float*)d_in[9];
    const float* iw1  = (const float*)d_in[10];
    const float* ib1  = (const float*)d_in[11];
    const float* ow1  = (const float*)d_in[12];
    const float* ob1  = (const float*)d_in[13];
    const float* cw1  = (const float*)d_in[14];
    const float* cb1  = (const float*)d_in[15];
    const float* cw2  = (const float*)d_in[16];
    const float* cb2  = (const float*)d_in[17];
    const float* cw3  = (const float*)d_in[18];
    const float* cb3  = (const float*)d_in[19];
    float* out = (float*)d_out;

    const int smem1 = SMEM1_FLOATS * 4;
    const int smem2 = SMEM2_FLOATS * 4;
    cudaFuncSetAttribute(hop2_kernel,
                         cudaFuncAttributeMaxDynamicSharedMemorySize, smem1);
    cudaFuncSetAttribute(hop1_kernel,
                         cudaFuncAttributeMaxDynamicSharedMemorySize, smem2);

    hop2_kernel<<<(NB * 16) / WPC, 256, smem1>>>(x2, lw2, lb2, iw2, ib2, ow2, ob2);
    hop1_kernel<<<NB / WPC, 256, smem2>>>(self, lw1, lb1, iw1, ib1, ow1, ob1,
                                          cw1, cb1, cw2, cb2, cw3, cb3, out);
}